// round 1
// baseline (speedup 1.0000x reference)
#include <cuda_runtime.h>

// Shapes (fixed for this problem)
#define LSEQ 512
#define CIN  256
#define HID  32
#define PAIR 64

// Scratch (static __device__ arrays — no allocation allowed)
__device__ float g_s[LSEQ * HID];            // s[i][h]
__device__ float g_tmp[LSEQ * PAIR * HID];   // tmp[i][k][c]

// ---- packed f32x2 helpers (Blackwell FFMA2) ----
static __device__ __forceinline__ unsigned long long pk2(float a, float b) {
    unsigned long long r;
    asm("mov.b64 %0, {%1, %2};" : "=l"(r) : "f"(a), "f"(b));
    return r;
}
static __device__ __forceinline__ void upk2(unsigned long long v, float& a, float& b) {
    asm("mov.b64 {%0, %1}, %2;" : "=f"(a), "=f"(b) : "l"(v));
}
static __device__ __forceinline__ unsigned long long ffma2(
    unsigned long long a, unsigned long long b, unsigned long long c) {
    unsigned long long r;
    asm("fma.rn.f32x2 %0, %1, %2, %3;" : "=l"(r) : "l"(a), "l"(b), "l"(c));
    return r;
}

// ============================================================
// K1: s[i][h] = dot(seq[i, :], W1[h, :]) + b1[h]
// grid 64 blocks x 256 threads; each block handles 8 rows of i.
// W1 staged transposed [d][h] in smem so the dot loop is conflict-free.
// ============================================================
__global__ __launch_bounds__(256) void k1_proj(
    const float* __restrict__ seq, const float* __restrict__ W1,
    const float* __restrict__ b1)
{
    __shared__ float seq_s[8 * CIN];     // 8 KB
    __shared__ float w1t[CIN * HID];     // 32 KB, [d][h]
    int tid = threadIdx.x;
    int i0 = blockIdx.x * 8;

    // stage seq rows (coalesced float4)
    const float4* sg = (const float4*)(seq + (size_t)i0 * CIN);
    float4* ss4 = (float4*)seq_s;
    #pragma unroll
    for (int t = tid; t < 8 * CIN / 4; t += 256) ss4[t] = sg[t];

    // stage W1 transposed: thread t -> (h = t&31, d4 = t>>5); STS conflict-free (h varies per lane)
    const float4* wg = (const float4*)W1;
    #pragma unroll
    for (int t = tid; t < HID * CIN / 4; t += 256) {
        int h = t & 31, d4 = t >> 5;
        float4 v = wg[h * (CIN / 4) + d4];
        w1t[(d4 * 4 + 0) * HID + h] = v.x;
        w1t[(d4 * 4 + 1) * HID + h] = v.y;
        w1t[(d4 * 4 + 2) * HID + h] = v.z;
        w1t[(d4 * 4 + 3) * HID + h] = v.w;
    }
    __syncthreads();

    int i = tid >> 5, h = tid & 31;
    float acc = b1[h];
    const float* sr = seq_s + i * CIN;
    #pragma unroll 8
    for (int d = 0; d < CIN; d++) acc += sr[d] * w1t[d * HID + h];
    g_s[(size_t)(i0 + i) * HID + h] = acc;
}

// ============================================================
// K2: tmp[i][k][c] = sum_d s[i][d] * W2[k][c*32 + d]
// Note linear W2 index: k*1024 + c*32 + d = (k*32+c)*32 + d = kc*32 + d.
// grid 64 blocks x 256 threads; block handles 8 i, each thread 8 kc values;
// a W2 row segment (32 floats) is loaded once and reused across all 8 i.
// ============================================================
__global__ __launch_bounds__(256) void k2_tmp(const float* __restrict__ W2)
{
    __shared__ float s8[8 * HID];   // 1 KB
    int tid = threadIdx.x;
    int i0 = blockIdx.x * 8;
    s8[tid] = g_s[(size_t)i0 * HID + tid];
    __syncthreads();

    const float4* s84 = (const float4*)s8;
    #pragma unroll
    for (int p = 0; p < 8; p++) {
        int kc = tid + p * 256;                  // 0..2047 == k*32 + c
        const float4* wr = (const float4*)(W2 + (size_t)kc * 32);
        float4 w[8];
        #pragma unroll
        for (int q = 0; q < 8; q++) w[q] = wr[q];
        #pragma unroll
        for (int i = 0; i < 8; i++) {
            float acc = 0.f;
            #pragma unroll
            for (int q = 0; q < 8; q++) {
                float4 sv = s84[i * 8 + q];      // warp-uniform -> smem broadcast
                acc += sv.x * w[q].x + sv.y * w[q].y + sv.z * w[q].z + sv.w * w[q].w;
            }
            g_tmp[(size_t)(i0 + i) * 2048 + kc] = acc;
        }
    }
}

// ============================================================
// K3 (dominant): out[i][j][k] = sum_c tmp[i][k][c]*s[j][c] + b2[k] + pair[i][j][k]
// grid (2, 512): blockIdx.y = i, blockIdx.x = j-tile of 256.
// 256 threads: tk = tid&7 (8 k each), tj = tid>>3 (8 j each).
// Inner loop over c uses packed f32x2 FMA: 32 FFMA2 == 64 FMA per thread per c.
// Epilogue fuses +b2 +pair_rep with float4 loads/stores.
// ============================================================
__global__ __launch_bounds__(256, 2) void k3_main(
    const float* __restrict__ pair_rep, const float* __restrict__ b2,
    float* __restrict__ out)
{
    __shared__ float s_sm[32 * 256];    // [c][j]  32 KB
    __shared__ float tmp_sm[32 * 64];   // [c][k]   8 KB
    int tid = threadIdx.x;
    int i  = blockIdx.y;
    int jt = blockIdx.x;

    // stage tmp[i] transposed: thread tid<64 handles k=tid (STS conflict-free)
    if (tid < 64) {
        const float4* tr = (const float4*)(g_tmp + (size_t)i * 2048 + (size_t)tid * 32);
        #pragma unroll
        for (int q = 0; q < 8; q++) {
            float4 v = tr[q];
            tmp_sm[(q * 4 + 0) * 64 + tid] = v.x;
            tmp_sm[(q * 4 + 1) * 64 + tid] = v.y;
            tmp_sm[(q * 4 + 2) * 64 + tid] = v.z;
            tmp_sm[(q * 4 + 3) * 64 + tid] = v.w;
        }
    }
    // stage s tile transposed: thread handles j = jt*256 + tid (STS conflict-free)
    {
        const float4* sr = (const float4*)(g_s + (size_t)(jt * 256 + tid) * 32);
        #pragma unroll
        for (int q = 0; q < 8; q++) {
            float4 v = sr[q];
            s_sm[(q * 4 + 0) * 256 + tid] = v.x;
            s_sm[(q * 4 + 1) * 256 + tid] = v.y;
            s_sm[(q * 4 + 2) * 256 + tid] = v.z;
            s_sm[(q * 4 + 3) * 256 + tid] = v.w;
        }
    }
    __syncthreads();

    int tk = tid & 7;        // k = tk*8 .. tk*8+7
    int tj = tid >> 3;       // j = jt*256 + tj*8 .. +7

    unsigned long long acc[8][4];
    #pragma unroll
    for (int a = 0; a < 8; a++)
        #pragma unroll
        for (int b = 0; b < 4; b++) acc[a][b] = 0ull;

    const float4* t4 = (const float4*)tmp_sm;   // row = 16 float4
    const float4* s4 = (const float4*)s_sm;     // row = 64 float4

    #pragma unroll 4
    for (int c = 0; c < 32; c++) {
        float4 ta = t4[c * 16 + tk * 2];
        float4 tb = t4[c * 16 + tk * 2 + 1];
        unsigned long long tp0 = pk2(ta.x, ta.y);
        unsigned long long tp1 = pk2(ta.z, ta.w);
        unsigned long long tp2 = pk2(tb.x, tb.y);
        unsigned long long tp3 = pk2(tb.z, tb.w);
        float4 sa = s4[c * 64 + tj * 2];
        float4 sb = s4[c * 64 + tj * 2 + 1];
        float sv[8] = {sa.x, sa.y, sa.z, sa.w, sb.x, sb.y, sb.z, sb.w};
        #pragma unroll
        for (int jj = 0; jj < 8; jj++) {
            unsigned long long sd = pk2(sv[jj], sv[jj]);
            acc[jj][0] = ffma2(sd, tp0, acc[jj][0]);
            acc[jj][1] = ffma2(sd, tp1, acc[jj][1]);
            acc[jj][2] = ffma2(sd, tp2, acc[jj][2]);
            acc[jj][3] = ffma2(sd, tp3, acc[jj][3]);
        }
    }

    // epilogue: + b2[k] + pair_rep, float4 stores
    const float4* b24 = (const float4*)b2;
    float4 bz0 = b24[tk * 2], bz1 = b24[tk * 2 + 1];
    #pragma unroll
    for (int jj = 0; jj < 8; jj++) {
        int j = jt * 256 + tj * 8 + jj;
        size_t off = (((size_t)i * 512 + (size_t)j) * 64) + (size_t)tk * 8;
        const float4* pr = (const float4*)(pair_rep + off);
        float4 p0 = pr[0], p1 = pr[1];
        float x0, x1, x2, x3, x4, x5, x6, x7;
        upk2(acc[jj][0], x0, x1);
        upk2(acc[jj][1], x2, x3);
        upk2(acc[jj][2], x4, x5);
        upk2(acc[jj][3], x6, x7);
        float4 o0 = make_float4(x0 + p0.x + bz0.x, x1 + p0.y + bz0.y,
                                x2 + p0.z + bz0.z, x3 + p0.w + bz0.w);
        float4 o1 = make_float4(x4 + p1.x + bz1.x, x5 + p1.y + bz1.y,
                                x6 + p1.z + bz1.z, x7 + p1.w + bz1.w);
        float4* orow = (float4*)(out + off);
        orow[0] = o0;
        orow[1] = o1;
    }
}

// ============================================================
// Launch: inputs in metadata order:
//   0 seq_rep [1,512,256] f32
//   1 pair_rep [1,512,512,64] f32
//   2 W1 [32,256] f32
//   3 b1 [32] f32
//   4 W2 [64,1024] f32
//   5 b2 [64] f32
// out: [1,512,512,64] f32
// ============================================================
extern "C" void kernel_launch(void* const* d_in, const int* in_sizes, int n_in,
                              void* d_out, int out_size)
{
    const float* seq  = (const float*)d_in[0];
    const float* pair = (const float*)d_in[1];
    const float* W1   = (const float*)d_in[2];
    const float* b1   = (const float*)d_in[3];
    const float* W2   = (const float*)d_in[4];
    const float* b2   = (const float*)d_in[5];
    float* out = (float*)d_out;

    k1_proj<<<LSEQ / 8, 256>>>(seq, W1, b1);
    k2_tmp<<<LSEQ / 8, 256>>>(W2);
    dim3 g3(2, LSEQ);
    k3_main<<<g3, 256>>>(pair, b2, out);
}